// round 13
// baseline (speedup 1.0000x reference)
#include <cuda_runtime.h>
#include <cuda_bf16.h>
#include <cuda_fp16.h>
#include <cstdint>

// ---------------- problem constants ----------------
#define NROWS   32768        // B*BARS*BEATS*FRAC
#define KF      940          // input features (10*2*47)
#define KPAD    960          // K padded to 30 x 32
#define NOUT    100          // linear out
#define K2PAD   112          // padded K for gemm2 (7 x 16)
#define BEATS_OUT_ELEMS (32768 * 16)
#define BARS_OUT_OFF    BEATS_OUT_ELEMS
#define SSTR    40           // smem row stride in b16 elems (80B, 16B-aligned)
#define ARR_ELEMS (128 * SSTR)   // 5120 elems per array
#define XGS     66           // gates smem row stride (floats, even)

// fused-kernel smem layout (float offsets)
#define OFF_XG   0                      // 128*66 = 8448
#define OFF_H    8448                   // 16*17  = 272
#define OFF_WIH  8720                   // 2*16*128 = 4096
#define OFF_WHH  12816                  // 2*32*128 = 8192
#define OFF_B    21008                  // 2*128 = 256
#define SM2_FLOATS 21264
#define SM2_BYTES  (SM2_FLOATS * 4)     // 85056 B

typedef unsigned int u32;

// ---------------- scratch ----------------
__device__ __half g_Whf[128 * KPAD];     // linear weight fp16 (permuted)
__device__ __half g_Wbh[64 * K2PAD];     // beats wih fp16 (padded)
__device__ float g_gb[64];
// Xlin as fp16, row stride K2PAD; pad cols [100,112) never written -> stay 0
__device__ __half g_Xh[(size_t)NROWS * K2PAD];

// ---------------- fast activations ----------------
__device__ __forceinline__ float tanha_(float x) {
    float y;
    asm("tanh.approx.f32 %0, %1;" : "=f"(y) : "f"(x));
    return y;
}
__device__ __forceinline__ float sig_(float x) {
    return fmaf(tanha_(0.5f * x), 0.5f, 0.5f);
}

// ---------------- K0: permute weights (fp16), beats weights ---------------
__global__ void prep_kernel(const float* __restrict__ lin_w,
                            const float* __restrict__ b_wih,
                            const float* __restrict__ b_bih,
                            const float* __restrict__ b_bhh) {
    int idx = blockIdx.x * blockDim.x + threadIdx.x;
    if (idx < 128 * KPAD) {
        int o = idx / KPAD;
        int m = idx % KPAD;
        float v = 0.0f;
        if (o < NOUT && m < KF) {
            int c10 = m / 94;
            int r   = m % 94;
            int c2  = r / 47;
            int c47 = r % 47;
            v = lin_w[o * KF + c10 * 94 + c47 * 2 + c2];
        }
        g_Whf[idx] = __float2half_rn(v);
    } else if (idx < 128 * KPAD + 64 * K2PAD) {
        int j = idx - 128 * KPAD;
        int n = j / K2PAD;
        int k = j % K2PAD;
        float v = (k < NOUT) ? b_wih[n * NOUT + k] : 0.0f;
        g_Wbh[j] = __float2half_rn(v);
    } else if (idx < 128 * KPAD + 64 * K2PAD + 64) {
        int j = idx - 128 * KPAD - 64 * K2PAD;
        g_gb[j] = b_bih[j] + b_bhh[j];
    }
}

// ---------------- mma helpers ----------------
__device__ __forceinline__ void ldsm4(u32& r0, u32& r1, u32& r2, u32& r3,
                                      u32 addr) {
    asm volatile("ldmatrix.sync.aligned.m8n8.x4.shared.b16 {%0,%1,%2,%3},[%4];"
                 : "=r"(r0), "=r"(r1), "=r"(r2), "=r"(r3) : "r"(addr));
}
__device__ __forceinline__ void ldsm2(u32& r0, u32& r1, u32 addr) {
    asm volatile("ldmatrix.sync.aligned.m8n8.x2.shared.b16 {%0,%1},[%2];"
                 : "=r"(r0), "=r"(r1) : "r"(addr));
}
__device__ __forceinline__ void mma_f16(float* c, const u32* a, const u32* b) {
    asm volatile(
        "mma.sync.aligned.m16n8k16.row.col.f32.f16.f16.f32 "
        "{%0,%1,%2,%3},{%4,%5,%6,%7},{%8,%9},{%0,%1,%2,%3};"
        : "+f"(c[0]), "+f"(c[1]), "+f"(c[2]), "+f"(c[3])
        : "r"(a[0]), "r"(a[1]), "r"(a[2]), "r"(a[3]), "r"(b[0]), "r"(b[1]));
}

// Register staging for the double-buffer prefetch in gemm1.
struct TileRegs {
    float x[16];
    uint4 wh[2];
};

__device__ __forceinline__ void load_tile(int K0, int lc,
                                          const float* __restrict__ xrow,
                                          const __half* __restrict__ wrow,
                                          TileRegs& t) {
#pragma unroll
    for (int j = 0; j < 4; j++) {
        int kb = K0 + lc + j * 4;
        if (kb + 3 < KF) {
            float4 v = *(const float4*)(xrow + K0 + j * 4);
            t.x[j * 4 + 0] = v.x; t.x[j * 4 + 1] = v.y;
            t.x[j * 4 + 2] = v.z; t.x[j * 4 + 3] = v.w;
        } else {
#pragma unroll
            for (int e = 0; e < 4; e++)
                t.x[j * 4 + e] = (kb + e < KF) ? xrow[K0 + j * 4 + e] : 0.0f;
        }
    }
    t.wh[0] = *(const uint4*)(wrow + K0);
    t.wh[1] = *(const uint4*)(wrow + K0 + 8);
}

// Packed: 2x STS.128 for X halves + 2x STS.128 for W.
__device__ __forceinline__ void store_tile(__half* bufbase, int off,
                                           const TileRegs& t) {
    __half* xp = bufbase + off;
    __half* wp = bufbase + ARR_ELEMS + off;
    u32 hw[8];
#pragma unroll
    for (int p = 0; p < 8; p++) {
        __half2 h = __floats2half2_rn(t.x[2 * p], t.x[2 * p + 1]);
        hw[p] = *(u32*)&h;
    }
    *(uint4*)xp       = make_uint4(hw[0], hw[1], hw[2], hw[3]);
    *(uint4*)(xp + 8) = make_uint4(hw[4], hw[5], hw[6], hw[7]);
    *(uint4*)wp       = t.wh[0];
    *(uint4*)(wp + 8) = t.wh[1];
}

// ---------------- K1: Xlin = relu(X @ W^T + b), single-pass fp16 mma -------
__global__ __launch_bounds__(256, 2)
void gemm1_kernel(const float* __restrict__ X, const float* __restrict__ lin_b) {
    __shared__ __align__(16) __half smem[2 * 2 * ARR_ELEMS];   // 40 KB

    const int tid  = threadIdx.x;
    const int row0 = blockIdx.x * 128;
    const int lr   = tid >> 1;        // 0..127 loader row
    const int lc   = (tid & 1) * 16;  // 0 / 16 loader col base
    const int soff = lr * SSTR + lc;

    const float* xrow = X + (size_t)(row0 + lr) * KF + lc;
    const __half* wrow = g_Whf + lr * KPAD + lc;

    // ldmatrix lane geometry
    const int lane = tid & 31;
    const int w    = tid >> 5;
    const int wm   = w & 3;       // 0..3 -> 32-row quarter
    const int wn   = w >> 2;      // 0..1 -> 64-col half
    const int NF   = wn ? 5 : 8;  // wn1: cols 64..103 only
    const int dra  = ((lane >> 3) & 1) * 8 + (lane & 7);
    const int dca  = (lane >> 4) * 8;
    const int aoff = (wm * 32 + dra) * SSTR + dca;
    const int l2   = lane & 15;
    const int boff = (wn * 64 + (l2 & 7)) * SSTR + (l2 >> 3) * 8;

    const u32 sbase = (u32)__cvta_generic_to_shared(smem);

    float acc[2][8][4];
#pragma unroll
    for (int a = 0; a < 2; a++)
#pragma unroll
        for (int b = 0; b < 8; b++)
#pragma unroll
            for (int c = 0; c < 4; c++) acc[a][b][c] = 0.0f;

    TileRegs t;
    load_tile(0, lc, xrow, wrow, t);
    store_tile(smem, soff, t);            // buffer 0 = tile 0
    load_tile(32, lc, xrow, wrow, t);     // tile 1 staged
    __syncthreads();

    for (int it = 0; it < 30; ++it) {
        if (it + 1 < 30) {
            store_tile(smem + ((it + 1) & 1) * (2 * ARR_ELEMS), soff, t);
            if (it + 2 < 30) load_tile((it + 2) * 32, lc, xrow, wrow, t);
        }

        const u32 cb = sbase + (u32)((it & 1) * (2 * ARR_ELEMS * 2));
#pragma unroll
        for (int kf = 0; kf < 32; kf += 16) {
            u32 af[2][4];
            u32 bf[8][2];
#pragma unroll
            for (int mf = 0; mf < 2; mf++) {
                u32 ea = (u32)(aoff + mf * 16 * SSTR + kf) * 2u;
                ldsm4(af[mf][0], af[mf][1], af[mf][2], af[mf][3], cb + ea);
            }
#pragma unroll
            for (int nf = 0; nf < 8; nf++)
                if (nf < NF) {
                    u32 eb = (u32)(boff + nf * 8 * SSTR + kf) * 2u
                             + (u32)(ARR_ELEMS * 2);
                    ldsm2(bf[nf][0], bf[nf][1], cb + eb);
                }
#pragma unroll
            for (int mf = 0; mf < 2; mf++)
#pragma unroll
                for (int nf = 0; nf < 8; nf++)
                    if (nf < NF)
                        mma_f16(acc[mf][nf], af[mf], bf[nf]);
        }
        __syncthreads();
    }

    // epilogue: relu + bias, fp16, cols < 100
    const int g  = lane >> 2;
    const int t4 = lane & 3;
#pragma unroll
    for (int mf = 0; mf < 2; mf++)
#pragma unroll
        for (int nf = 0; nf < 8; nf++)
            if (nf < NF) {
                int col = wn * 64 + nf * 8 + t4 * 2;
                if (col < NOUT) {
                    float b0 = __ldg(lin_b + col), b1 = __ldg(lin_b + col + 1);
                    int r1 = row0 + wm * 32 + mf * 16 + g;
                    float v0 = fmaxf(acc[mf][nf][0] + b0, 0.0f);
                    float v1 = fmaxf(acc[mf][nf][1] + b1, 0.0f);
                    float v2 = fmaxf(acc[mf][nf][2] + b0, 0.0f);
                    float v3 = fmaxf(acc[mf][nf][3] + b1, 0.0f);
                    *(__half2*)(g_Xh + (size_t)r1 * K2PAD + col) =
                        __floats2half2_rn(v0, v1);
                    *(__half2*)(g_Xh + (size_t)(r1 + 8) * K2PAD + col) =
                        __floats2half2_rn(v2, v3);
                }
            }
}

// ---------------- K2: fused gates GEMM + beats LSTM + bars biLSTM ----------
// Block = 128 rows = 16 beat-seqs = 4 complete bars. Phase 1: mma gates ->
// smem. Phase 2: beats LSTM (2 seqs/warp), final h -> sH. Phase 3: 8 warps
// = 4 bars x 2 dirs run the bars biLSTM from sH with smem weights.
__global__ __launch_bounds__(256)
void gemm2_beats(const float* __restrict__ whh,
                 const float* __restrict__ f_wih,
                 const float* __restrict__ f_whh,
                 const float* __restrict__ f_bih,
                 const float* __restrict__ f_bhh,
                 const float* __restrict__ r_wih,
                 const float* __restrict__ r_whh,
                 const float* __restrict__ r_bih,
                 const float* __restrict__ r_bhh,
                 float* __restrict__ out) {
    extern __shared__ float smf[];
    float* sXG = smf + OFF_XG;
    float* sH  = smf + OFF_H;

    const int tid  = threadIdx.x;
    const int lane = tid & 31;
    const int w    = tid >> 5;
    const int wm   = w & 3;
    const int wn   = w >> 2;
    const int g    = lane >> 2;
    const int t4   = lane & 3;
    const int rloc = wm * 32;
    const int row0 = blockIdx.x * 128 + rloc;

    // ---- stage bars weights into smem (transposed [j][gate]) ----
    for (int i = tid; i < 16 * 128; i += 256) {
        int gg = i >> 4, j = i & 15;
        smf[OFF_WIH + j * 128 + gg]        = f_wih[i];
        smf[OFF_WIH + 2048 + j * 128 + gg] = r_wih[i];
    }
    for (int i = tid; i < 32 * 128; i += 256) {
        int gg = i >> 5, j = i & 31;
        smf[OFF_WHH + j * 128 + gg]        = f_whh[i];
        smf[OFF_WHH + 4096 + j * 128 + gg] = r_whh[i];
    }
    if (tid < 128) {
        smf[OFF_B + tid]       = f_bih[tid] + f_bhh[tid];
        smf[OFF_B + 128 + tid] = r_bih[tid] + r_bhh[tid];
    }

    // ---- phase 1: gates GEMM ----
    float acc[2][4][4];
#pragma unroll
    for (int a = 0; a < 2; a++)
#pragma unroll
        for (int b = 0; b < 4; b++)
#pragma unroll
            for (int c = 0; c < 4; c++) acc[a][b][c] = 0.0f;

#pragma unroll
    for (int kc = 0; kc < 7; kc++) {
        const int k0 = kc * 16 + t4 * 2;
        u32 af[2][4], bf[4][2];
#pragma unroll
        for (int mf = 0; mf < 2; mf++) {
            size_t base = (size_t)(row0 + mf * 16 + g) * K2PAD + k0;
            af[mf][0] = *(const u32*)(g_Xh + base);
            af[mf][1] = *(const u32*)(g_Xh + base + 8 * K2PAD);
            af[mf][2] = *(const u32*)(g_Xh + base + 8);
            af[mf][3] = *(const u32*)(g_Xh + base + 8 * K2PAD + 8);
        }
#pragma unroll
        for (int nf = 0; nf < 4; nf++) {
            int nbase = (wn * 32 + nf * 8 + g) * K2PAD + k0;
            bf[nf][0] = *(const u32*)(g_Wbh + nbase);
            bf[nf][1] = *(const u32*)(g_Wbh + nbase + 8);
        }
#pragma unroll
        for (int mf = 0; mf < 2; mf++)
#pragma unroll
            for (int nf = 0; nf < 4; nf++)
                mma_f16(acc[mf][nf], af[mf], bf[nf]);
    }

#pragma unroll
    for (int mf = 0; mf < 2; mf++)
#pragma unroll
        for (int nf = 0; nf < 4; nf++) {
            int col = wn * 32 + nf * 8 + t4 * 2;
            float b0 = g_gb[col], b1 = g_gb[col + 1];
            int r = rloc + mf * 16 + g;
            *(float2*)(sXG + r * XGS + col) =
                make_float2(acc[mf][nf][0] + b0, acc[mf][nf][1] + b1);
            *(float2*)(sXG + (r + 8) * XGS + col) =
                make_float2(acc[mf][nf][2] + b0, acc[mf][nf][3] + b1);
        }
    __syncthreads();

    // ---- phase 2: beats LSTM (warp w: local seqs 2w, 2w+1 interleaved) ----
    float w0[16], w1[16];
#pragma unroll
    for (int j = 0; j < 16; j++) {
        w0[j] = whh[lane * 16 + j];
        w1[j] = whh[(lane + 32) * 16 + j];
    }
    const bool lo = lane < 16;

    const int sl0 = w * 2, sl1 = w * 2 + 1;
    float pa0[8], pb0[8], pa1[8], pb1[8];
#pragma unroll
    for (int t = 0; t < 8; t++) {
        pa0[t] = sXG[(sl0 * 8 + t) * XGS + lane];
        pb0[t] = sXG[(sl0 * 8 + t) * XGS + lane + 32];
        pa1[t] = sXG[(sl1 * 8 + t) * XGS + lane];
        pb1[t] = sXG[(sl1 * 8 + t) * XGS + lane + 32];
    }
    float h0 = 0.0f, c0 = 0.0f, h1 = 0.0f, c1 = 0.0f;
    float* ob0 = out + ((size_t)blockIdx.x * 16 + sl0) * 128;
    float* ob1 = out + ((size_t)blockIdx.x * 16 + sl1) * 128;

#pragma unroll
    for (int t = 0; t < 8; t++) {
        float ga0 = pa0[t], gb0 = pb0[t];
        float ga1 = pa1[t], gb1 = pb1[t];
#pragma unroll
        for (int j = 0; j < 16; j++) {
            float hj0 = __shfl_sync(0xffffffffu, h0, j);
            float hj1 = __shfl_sync(0xffffffffu, h1, j);
            ga0 = fmaf(w0[j], hj0, ga0);
            gb0 = fmaf(w1[j], hj0, gb0);
            ga1 = fmaf(w0[j], hj1, ga1);
            gb1 = fmaf(w1[j], hj1, gb1);
        }
        float A0, B0, A1, B1;
        if (lo) {
            A0 = sig_(ga0) * tanha_(gb0);  B0 = 0.0f;
            A1 = sig_(ga1) * tanha_(gb1);  B1 = 0.0f;
        } else {
            A0 = sig_(ga0);  B0 = sig_(gb0);
            A1 = sig_(ga1);  B1 = sig_(gb1);
        }
        float f0 = __shfl_sync(0xffffffffu, A0, lane + 16);
        float o0 = __shfl_sync(0xffffffffu, B0, lane + 16);
        float f1 = __shfl_sync(0xffffffffu, A1, lane + 16);
        float o1 = __shfl_sync(0xffffffffu, B1, lane + 16);
        if (lo) {
            c0 = fmaf(f0, c0, A0);
            h0 = o0 * tanha_(c0);
            ob0[t * 16 + lane] = h0;
            c1 = fmaf(f1, c1, A1);
            h1 = o1 * tanha_(c1);
            ob1[t * 16 + lane] = h1;
        }
    }
    // park final h (last fraction) for the bars phase
    if (lo) {
        sH[sl0 * 17 + lane] = h0;
        sH[sl1 * 17 + lane] = h1;
    }
    __syncthreads();

    // ---- phase 3: bars biLSTM. warp w: bar = w&3 (local), dir = w>>2 ----
    {
        const int bar = w & 3;
        const int dir = w >> 2;
        const float* wihs = smf + OFF_WIH + dir * 2048;
        const float* whhs = smf + OFF_WHH + dir * 4096;
        const float* bs   = smf + OFF_B + dir * 128;
        const int nglob = blockIdx.x * 4 + bar;
        float* bars = out + BARS_OUT_OFF;

        float bi = bs[lane], bfv = bs[32 + lane];
        float bg = bs[64 + lane], bo = bs[96 + lane];

        float hh = 0.0f, cc = 0.0f;
        for (int s = 0; s < 4; s++) {
            int t = dir ? (3 - s) : s;
            float xv = (lane < 16) ? sH[(bar * 4 + t) * 17 + lane] : 0.0f;

            float gi = bi, gf = bfv, gg2 = bg, go = bo;
#pragma unroll
            for (int j = 0; j < 16; j++) {
                float xj = __shfl_sync(0xffffffffu, xv, j);
                gi  = fmaf(wihs[j * 128 + lane],      xj, gi);
                gf  = fmaf(wihs[j * 128 + 32 + lane], xj, gf);
                gg2 = fmaf(wihs[j * 128 + 64 + lane], xj, gg2);
                go  = fmaf(wihs[j * 128 + 96 + lane], xj, go);
            }
#pragma unroll
            for (int j = 0; j < 32; j++) {
                float hj = __shfl_sync(0xffffffffu, hh, j);
                gi  = fmaf(whhs[j * 128 + lane],      hj, gi);
                gf  = fmaf(whhs[j * 128 + 32 + lane], hj, gf);
                gg2 = fmaf(whhs[j * 128 + 64 + lane], hj, gg2);
                go  = fmaf(whhs[j * 128 + 96 + lane], hj, go);
            }
            cc = fmaf(sig_(gf), cc, sig_(gi) * tanha_(gg2));
            hh = sig_(go) * tanha_(cc);
            bars[((size_t)nglob * 4 + t) * 64 + dir * 32 + lane] = hh;
        }
    }
}

// ---------------- launch ----------------------------------------------------
extern "C" void kernel_launch(void* const* d_in, const int* in_sizes, int n_in,
                              void* d_out, int out_size) {
    const float* channels = (const float*)d_in[0];
    const float* lin_w    = (const float*)d_in[1];
    const float* lin_b    = (const float*)d_in[2];
    const float* b_wih    = (const float*)d_in[3];
    const float* b_whh    = (const float*)d_in[4];
    const float* b_bih    = (const float*)d_in[5];
    const float* b_bhh    = (const float*)d_in[6];
    const float* f_wih    = (const float*)d_in[7];
    const float* f_whh    = (const float*)d_in[8];
    const float* f_bih    = (const float*)d_in[9];
    const float* f_bhh    = (const float*)d_in[10];
    const float* r_wih    = (const float*)d_in[11];
    const float* r_whh    = (const float*)d_in[12];
    const float* r_bih    = (const float*)d_in[13];
    const float* r_bhh    = (const float*)d_in[14];
    float* out = (float*)d_out;

    cudaFuncSetAttribute(gemm2_beats,
                         cudaFuncAttributeMaxDynamicSharedMemorySize, SM2_BYTES);

    int prep_n = 128 * KPAD + 64 * K2PAD + 64;
    prep_kernel<<<(prep_n + 255) / 256, 256>>>(lin_w, b_wih, b_bih, b_bhh);
    gemm1_kernel<<<NROWS / 128, 256>>>(channels, lin_b);
    gemm2_beats<<<NROWS / 128, 256, SM2_BYTES>>>(
        b_whh, f_wih, f_whh, f_bih, f_bhh,
        r_wih, r_whh, r_bih, r_bhh, out);
}